// round 1
// baseline (speedup 1.0000x reference)
#include <cuda_runtime.h>

// ---------------------------------------------------------------------------
// Problem constants
// ---------------------------------------------------------------------------
#define EDIM   1024
#define FFDIM  4096
#define BATCH  4
#define SEQ    2048
#define ROWS   (BATCH * SEQ)          // 8192
#define EPSV   1e-5f

// ---------------------------------------------------------------------------
// Scratch (static device globals: no allocation in kernel_launch)
// ---------------------------------------------------------------------------
__device__ float g_Q   [(size_t)ROWS * EDIM];
__device__ float g_K   [(size_t)ROWS * EDIM];
__device__ float g_V   [(size_t)ROWS * EDIM];
__device__ float g_S   [(size_t)BATCH * SEQ * SEQ];   // scores / probs (67 MB)
__device__ float g_attn[(size_t)ROWS * EDIM];
__device__ float g_tmp [(size_t)ROWS * EDIM];
__device__ float g_x   [(size_t)ROWS * EDIM];
__device__ float g_ff  [(size_t)ROWS * FFDIM];

// ---------------------------------------------------------------------------
// SGEMM: C[M,N] = A[M,K] * op(B) (+ bias) (+ relu)
//   TRANSB = false : B is [K,N] row-major        (NN)
//   TRANSB = true  : B is [N,K] row-major, use B^T (NT)
// Batched via gridDim.z with element strides sA/sB/sC.
// Requires: M % 128 == 0, N % 128 == 0, K % 8 == 0 (true for all our shapes).
// Tile: 128x128x8, 256 threads, 8x8 accumulator per thread.
// ---------------------------------------------------------------------------
template<bool TRANSB, bool RELU>
__global__ __launch_bounds__(256)
void sgemm_k(const float* __restrict__ A, const float* __restrict__ B,
             const float* __restrict__ bias, float* __restrict__ C,
             int M, int N, int K, size_t sA, size_t sB, size_t sC)
{
    __shared__ float As[8][128];
    __shared__ float Bs[8][128];

    const int tid = threadIdx.x;
    const int ty  = tid >> 4;        // 0..15  -> row group of 8
    const int tx  = tid & 15;        // 0..15  -> col group of 8

    const float* Ag = A + blockIdx.z * sA + (size_t)(blockIdx.y * 128) * K;
    const float* Bg = B + blockIdx.z * sB;
    float*       Cg = C + blockIdx.z * sC + (size_t)(blockIdx.y * 128) * N
                        + (size_t)(blockIdx.x * 128);

    const int lr = tid >> 1;         // 0..127 (row within tile for A / NT-B loads)
    const int lc = (tid & 1) * 4;    // 0 or 4 (k offset, float4 granularity)

    float acc[8][8];
    #pragma unroll
    for (int i = 0; i < 8; i++)
        #pragma unroll
        for (int j = 0; j < 8; j++) acc[i][j] = 0.f;

    for (int k0 = 0; k0 < K; k0 += 8) {
        // --- load A tile (128 rows x 8 k), store k-major for conflict-free LDS
        float4 av = *(const float4*)(Ag + (size_t)lr * K + (k0 + lc));
        As[lc + 0][lr] = av.x;
        As[lc + 1][lr] = av.y;
        As[lc + 2][lr] = av.z;
        As[lc + 3][lr] = av.w;

        // --- load B tile
        if (TRANSB) {
            // B[N,K]: tile rows are output columns
            float4 bv = *(const float4*)(Bg + (size_t)(blockIdx.x * 128 + lr) * K + (k0 + lc));
            Bs[lc + 0][lr] = bv.x;
            Bs[lc + 1][lr] = bv.y;
            Bs[lc + 2][lr] = bv.z;
            Bs[lc + 3][lr] = bv.w;
        } else {
            // B[K,N]: 8 rows of 128 floats
            const int brow = tid >> 5;        // 0..7
            const int bcol = (tid & 31) * 4;  // 0..124
            float4 bv = *(const float4*)(Bg + (size_t)(k0 + brow) * N
                                            + (size_t)(blockIdx.x * 128 + bcol));
            *(float4*)&Bs[brow][bcol] = bv;
        }
        __syncthreads();

        // --- compute
        #pragma unroll
        for (int k = 0; k < 8; k++) {
            float4 a0 = *(const float4*)&As[k][ty * 8];
            float4 a1 = *(const float4*)&As[k][ty * 8 + 4];
            float4 b0 = *(const float4*)&Bs[k][tx * 8];
            float4 b1 = *(const float4*)&Bs[k][tx * 8 + 4];
            float ar[8] = {a0.x, a0.y, a0.z, a0.w, a1.x, a1.y, a1.z, a1.w};
            float br[8] = {b0.x, b0.y, b0.z, b0.w, b1.x, b1.y, b1.z, b1.w};
            #pragma unroll
            for (int i = 0; i < 8; i++)
                #pragma unroll
                for (int j = 0; j < 8; j++)
                    acc[i][j] = fmaf(ar[i], br[j], acc[i][j]);
        }
        __syncthreads();
    }

    // --- epilogue: bias + optional relu, float4 stores
    float bb[8];
    #pragma unroll
    for (int j = 0; j < 8; j++) bb[j] = 0.f;
    if (bias != nullptr) {
        #pragma unroll
        for (int j = 0; j < 8; j++)
            bb[j] = bias[blockIdx.x * 128 + tx * 8 + j];
    }

    #pragma unroll
    for (int i = 0; i < 8; i++) {
        float* cp = Cg + (size_t)(ty * 8 + i) * N + tx * 8;
        float v[8];
        #pragma unroll
        for (int j = 0; j < 8; j++) {
            v[j] = acc[i][j] + bb[j];
            if (RELU) v[j] = fmaxf(v[j], 0.f);
        }
        *(float4*)(cp + 0) = make_float4(v[0], v[1], v[2], v[3]);
        *(float4*)(cp + 4) = make_float4(v[4], v[5], v[6], v[7]);
    }
}

// ---------------------------------------------------------------------------
// Row softmax over SEQ=2048 columns, in place. One block (256 threads) per row.
// 8 elements per thread live in registers: one global read + one write.
// ---------------------------------------------------------------------------
__global__ __launch_bounds__(256)
void softmax_k(float* __restrict__ S)
{
    float* p = S + (size_t)blockIdx.x * SEQ;
    const int tid = threadIdx.x;
    __shared__ float red[256];

    float r[8];
    float m = -1e30f;
    #pragma unroll
    for (int i = 0; i < 8; i++) {
        r[i] = p[tid + i * 256];
        m = fmaxf(m, r[i]);
    }
    red[tid] = m;
    __syncthreads();
    #pragma unroll
    for (int s = 128; s > 0; s >>= 1) {
        if (tid < s) red[tid] = fmaxf(red[tid], red[tid + s]);
        __syncthreads();
    }
    m = red[0];
    __syncthreads();

    float sum = 0.f;
    #pragma unroll
    for (int i = 0; i < 8; i++) {
        r[i] = __expf(r[i] - m);
        sum += r[i];
    }
    red[tid] = sum;
    __syncthreads();
    #pragma unroll
    for (int s = 128; s > 0; s >>= 1) {
        if (tid < s) red[tid] += red[tid + s];
        __syncthreads();
    }
    const float inv = 1.f / red[0];
    #pragma unroll
    for (int i = 0; i < 8; i++)
        p[tid + i * 256] = r[i] * inv;
}

// ---------------------------------------------------------------------------
// out = LayerNorm(a + b) * g + beta, rows of EDIM=1024. 256 threads/row.
// ---------------------------------------------------------------------------
__global__ __launch_bounds__(256)
void add_ln_k(const float* __restrict__ a, const float* __restrict__ b,
              const float* __restrict__ g, const float* __restrict__ beta,
              float* __restrict__ out)
{
    const size_t base = (size_t)blockIdx.x * EDIM;
    const int tid = threadIdx.x;
    __shared__ float r1[256];
    __shared__ float r2[256];

    float v[4];
    float s = 0.f, sq = 0.f;
    #pragma unroll
    for (int i = 0; i < 4; i++) {
        const int c = tid + i * 256;
        v[i] = a[base + c] + b[base + c];
        s  += v[i];
        sq += v[i] * v[i];
    }
    r1[tid] = s;
    r2[tid] = sq;
    __syncthreads();
    #pragma unroll
    for (int st = 128; st > 0; st >>= 1) {
        if (tid < st) { r1[tid] += r1[tid + st]; r2[tid] += r2[tid + st]; }
        __syncthreads();
    }
    const float mu  = r1[0] * (1.f / EDIM);
    const float var = r2[0] * (1.f / EDIM) - mu * mu;
    const float inv = rsqrtf(var + EPSV);
    #pragma unroll
    for (int i = 0; i < 4; i++) {
        const int c = tid + i * 256;
        out[base + c] = (v[i] - mu) * inv * g[c] + beta[c];
    }
}

// ---------------------------------------------------------------------------
// Launch sequence
// ---------------------------------------------------------------------------
extern "C" void kernel_launch(void* const* d_in, const int* in_sizes, int n_in,
                              void* d_out, int out_size)
{
    (void)in_sizes; (void)n_in; (void)out_size;

    const float* src = (const float*)d_in[0];
    const float* Wq  = (const float*)d_in[1];
    const float* bq  = (const float*)d_in[2];
    const float* Wk  = (const float*)d_in[3];
    const float* bk  = (const float*)d_in[4];
    const float* Wv  = (const float*)d_in[5];
    const float* bv  = (const float*)d_in[6];
    const float* Wo  = (const float*)d_in[7];
    const float* bo  = (const float*)d_in[8];
    const float* W1  = (const float*)d_in[9];
    const float* b1  = (const float*)d_in[10];
    const float* W2  = (const float*)d_in[11];
    const float* b2  = (const float*)d_in[12];
    const float* g1  = (const float*)d_in[13];
    const float* be1 = (const float*)d_in[14];
    const float* g2  = (const float*)d_in[15];
    const float* be2 = (const float*)d_in[16];
    float* out = (float*)d_out;

    float *Q, *K, *V, *S, *attn, *tmp, *x, *ff;
    cudaGetSymbolAddress((void**)&Q,    g_Q);
    cudaGetSymbolAddress((void**)&K,    g_K);
    cudaGetSymbolAddress((void**)&V,    g_V);
    cudaGetSymbolAddress((void**)&S,    g_S);
    cudaGetSymbolAddress((void**)&attn, g_attn);
    cudaGetSymbolAddress((void**)&tmp,  g_tmp);
    cudaGetSymbolAddress((void**)&x,    g_x);
    cudaGetSymbolAddress((void**)&ff,   g_ff);

    const dim3 blk(256);

    // 1-3. Q/K/V projections: [8192,1024] = src @ W[1024,1024] + b
    {
        dim3 grd(EDIM / 128, ROWS / 128, 1);
        sgemm_k<false, false><<<grd, blk>>>(src, Wq, bq, Q, ROWS, EDIM, EDIM, 0, 0, 0);
        sgemm_k<false, false><<<grd, blk>>>(src, Wk, bk, K, ROWS, EDIM, EDIM, 0, 0, 0);
        sgemm_k<false, false><<<grd, blk>>>(src, Wv, bv, V, ROWS, EDIM, EDIM, 0, 0, 0);
    }

    // 4. scores: per batch, S_b[2048,2048] = Q_b @ K_b^T   (NO 1/sqrt(d) scaling)
    {
        dim3 grd(SEQ / 128, SEQ / 128, BATCH);
        sgemm_k<true, false><<<grd, blk>>>(
            Q, K, nullptr, S, SEQ, SEQ, EDIM,
            (size_t)SEQ * EDIM, (size_t)SEQ * EDIM, (size_t)SEQ * SEQ);
    }

    // 5. row softmax over 8192 rows of 2048
    softmax_k<<<ROWS, blk>>>(S);

    // 6. attn: per batch, attn_b[2048,1024] = P_b @ V_b
    {
        dim3 grd(EDIM / 128, SEQ / 128, BATCH);
        sgemm_k<false, false><<<grd, blk>>>(
            S, V, nullptr, attn, SEQ, EDIM, SEQ,
            (size_t)SEQ * SEQ, (size_t)SEQ * EDIM, (size_t)SEQ * EDIM);
    }

    // 7. output projection: tmp = attn @ Wo + bo
    {
        dim3 grd(EDIM / 128, ROWS / 128, 1);
        sgemm_k<false, false><<<grd, blk>>>(attn, Wo, bo, tmp, ROWS, EDIM, EDIM, 0, 0, 0);
    }

    // 8. x = LN(src + tmp) * g1 + be1
    add_ln_k<<<ROWS, blk>>>(src, tmp, g1, be1, x);

    // 9. ff = relu(x @ W1 + b1)   [8192,4096]
    {
        dim3 grd(FFDIM / 128, ROWS / 128, 1);
        sgemm_k<false, true><<<grd, blk>>>(x, W1, b1, ff, ROWS, FFDIM, EDIM, 0, 0, 0);
    }

    // 10. tmp = ff @ W2 + b2      [8192,1024]
    {
        dim3 grd(EDIM / 128, ROWS / 128, 1);
        sgemm_k<false, false><<<grd, blk>>>(ff, W2, b2, tmp, ROWS, EDIM, FFDIM, 0, 0, 0);
    }

    // 11. out = LN(x + tmp) * g2 + be2
    add_ln_k<<<ROWS, blk>>>(x, tmp, g2, be2, out);
}